// round 6
// baseline (speedup 1.0000x reference)
#include <cuda_runtime.h>
#include <math.h>
#include <float.h>

#define N_PTS 4096
#define BATCH 4
#define C_IN  64
#define C_OUT 128
#define KNN   20
#define C_BOT 16
#define EPSBN 1e-5f

// ---------------- scratch (device globals; no allocation) ----------------
__device__ float g_sq[BATCH * N_PTS];                       // 64 KB
__device__ float g_hb[BATCH * N_PTS * C_BOT];               // 1 MB, [B*N,16]
__device__ int   g_idx[BATCH * N_PTS * KNN];                // 1.3 MB
__device__ float g_allf[(size_t)BATCH * N_PTS * 96];        // 25 MB, [B*N,96]
__device__ float g_Wt[160 * 128];                           // folded [k][o]
__device__ float g_bias[256];                               // tDec[128], tRes[128]

// ---------------- f32x2 helpers (Blackwell packed FMA path) -----------------
__device__ __forceinline__ unsigned long long pk2(float x, float y) {
    unsigned long long r;
    asm("mov.b64 %0, {%1,%2};" : "=l"(r) : "f"(x), "f"(y));
    return r;
}
__device__ __forceinline__ void upk2(unsigned long long v, float& x, float& y) {
    asm("mov.b64 {%0,%1}, %2;" : "=f"(x), "=f"(y) : "l"(v));
}
__device__ __forceinline__ unsigned long long fma2(unsigned long long a,
                                                   unsigned long long b,
                                                   unsigned long long c) {
    unsigned long long d;
    asm("fma.rn.f32x2 %0, %1, %2, %3;" : "=l"(d) : "l"(a), "l"(b), "l"(c));
    return d;
}

// ---------------- K1: sq norms + bottleneck conv (BN+ReLU), hb transposed ----
__global__ void k_prep(const float* __restrict__ x,
                       const float* __restrict__ Wb, const float* __restrict__ gb,
                       const float* __restrict__ bb, const float* __restrict__ mb,
                       const float* __restrict__ vb)
{
    __shared__ float sW[C_BOT][C_IN];
    __shared__ float sS[C_BOT], sT[C_BOT];
    int tid = threadIdx.x;
    if (tid < C_BOT) {
        float s = gb[tid] * rsqrtf(vb[tid] + EPSBN);
        sS[tid] = s;
        sT[tid] = bb[tid] - mb[tid] * s;
    }
    for (int e = tid; e < C_BOT * C_IN; e += blockDim.x)
        sW[e >> 6][e & 63] = Wb[e];
    __syncthreads();

    int g = blockIdx.x * blockDim.x + tid;      // 0 .. BATCH*N_PTS-1
    if (g >= BATCH * N_PTS) return;
    int b = g >> 12, n = g & (N_PTS - 1);
    const float* xp = x + (size_t)b * C_IN * N_PTS + n;

    float xc[C_IN];
    float sq = 0.f;
#pragma unroll
    for (int c = 0; c < C_IN; c++) {
        float v = xp[(size_t)c * N_PTS];
        xc[c] = v;
        sq += v * v;                 // same ascending-c order as GEMM dot
    }
    g_sq[g] = sq;

#pragma unroll
    for (int o = 0; o < C_BOT; o++) {
        float acc = 0.f;
#pragma unroll
        for (int c = 0; c < C_IN; c++) acc += sW[o][c] * xc[c];
        float h = acc * sS[o] + sT[o];
        g_hb[(size_t)g * C_BOT + o] = fmaxf(h, 0.f);
    }
}

// ------- K2: FUSED pairwise distances + streaming top-K (no d2 in HBM) ------
// Block: 256 threads, owns 64 rows for all 4096 columns.
__global__ void __launch_bounds__(256) k_fused(const float* __restrict__ x)
{
    extern __shared__ char smraw[];
    unsigned long long* sList = (unsigned long long*)smraw;            // 64*20
    unsigned long long* sThr  = sList + 64 * KNN;                      // 64
    float* As    = (float*)(sThr + 64);                                // 64*64
    float* Bs    = As + 64 * 64;                                       // 64*64
    float* stage = Bs + 64 * 64;                                       // 64*68
    float* sqA   = stage + 64 * 68;                                    // 64
    float* sqB   = sqA + 64;                                           // 64

    int tid = threadIdx.x;
    int bi  = blockIdx.x;            // row tile
    int b   = blockIdx.y;            // batch
    const float* xb = x + (size_t)b * C_IN * N_PTS;

    // init lists to +inf keys
    for (int e = tid; e < 64 * KNN; e += 256) sList[e] = ~0ULL;
    if (tid < 64) sThr[tid] = ~0ULL;

    // load A tile (64 rows x 64 dims) once
    for (int e = tid; e < 64 * 64; e += 256) {
        int i = e & 63, k = e >> 6;
        As[k * 64 + i] = xb[(size_t)k * N_PTS + bi * 64 + i];
    }
    if (tid < 64) sqA[tid] = g_sq[b * N_PTS + bi * 64 + tid];
    __syncthreads();

    int tx = tid & 15, ty = tid >> 4;
    int lane = tid & 31, w = tid >> 5;

    for (int bj = 0; bj < N_PTS / 64; bj++) {
        // ---- load B tile + sqB ----
        for (int e = tid; e < 64 * 64; e += 256) {
            int i = e & 63, k = e >> 6;
            Bs[k * 64 + i] = xb[(size_t)k * N_PTS + bj * 64 + i];
        }
        if (tid < 64) sqB[tid] = g_sq[b * N_PTS + bj * 64 + tid];
        __syncthreads();

        // ---- GEMM: 4x4 per thread, f32x2 (identical math to R5 k_dist) ----
        unsigned long long acc2[4][2];
#pragma unroll
        for (int i = 0; i < 4; i++) { acc2[i][0] = 0ULL; acc2[i][1] = 0ULL; }

#pragma unroll 16
        for (int k = 0; k < 64; k++) {
            float2 a01 = *(const float2*)&As[k * 64 + ty * 4];
            float2 a23 = *(const float2*)&As[k * 64 + ty * 4 + 2];
            float2 b01 = *(const float2*)&Bs[k * 64 + tx * 4];
            float2 b23 = *(const float2*)&Bs[k * 64 + tx * 4 + 2];
            unsigned long long B01 = pk2(b01.x, b01.y);
            unsigned long long B23 = pk2(b23.x, b23.y);
            unsigned long long A0 = pk2(a01.x, a01.x);
            unsigned long long A1 = pk2(a01.y, a01.y);
            unsigned long long A2 = pk2(a23.x, a23.x);
            unsigned long long A3 = pk2(a23.y, a23.y);
            acc2[0][0] = fma2(A0, B01, acc2[0][0]);
            acc2[0][1] = fma2(A0, B23, acc2[0][1]);
            acc2[1][0] = fma2(A1, B01, acc2[1][0]);
            acc2[1][1] = fma2(A1, B23, acc2[1][1]);
            acc2[2][0] = fma2(A2, B01, acc2[2][0]);
            acc2[2][1] = fma2(A2, B23, acc2[2][1]);
            acc2[3][0] = fma2(A3, B01, acc2[3][0]);
            acc2[3][1] = fma2(A3, B23, acc2[3][1]);
        }

        // ---- epilogue -> stage tile in shared ----
#pragma unroll
        for (int ri = 0; ri < 4; ri++) {
            int r = ty * 4 + ri;
            float sr = sqA[r];
            float c0, c1, c2, c3;
            upk2(acc2[ri][0], c0, c1);
            upk2(acc2[ri][1], c2, c3);
            float4 v;
            v.x = sr + sqB[tx * 4 + 0] - 2.f * c0;
            v.y = sr + sqB[tx * 4 + 1] - 2.f * c1;
            v.z = sr + sqB[tx * 4 + 2] - 2.f * c2;
            v.w = sr + sqB[tx * 4 + 3] - 2.f * c3;
            *(float4*)&stage[r * 68 + tx * 4] = v;
        }
        __syncthreads();

        // ---- filter phase: warp w owns rows w*8 .. w*8+7 ----
#pragma unroll 1
        for (int rr = 0; rr < 8; rr++) {
            int r = w * 8 + rr;
#pragma unroll
            for (int round = 0; round < 2; round++) {
                float dv = stage[r * 68 + round * 32 + lane];
                unsigned uk = __float_as_uint(dv);
                uk = (uk & 0x80000000u) ? ~uk : (uk | 0x80000000u);
                unsigned long long pn = ((unsigned long long)uk << 32) |
                                        (unsigned)(bj * 64 + round * 32 + lane);
                unsigned long long thr = sThr[r];
                unsigned hit = __ballot_sync(0xffffffffu, pn < thr);
                while (hit) {
                    int src = __ffs(hit) - 1;
                    hit &= hit - 1;
                    unsigned long long pns = __shfl_sync(0xffffffffu, pn, src);
                    if (pns >= sThr[r]) continue;          // tightened
                    unsigned long long ent = (lane < KNN) ? sList[r * KNN + lane]
                                                          : ~0ULL;
                    unsigned pm = __ballot_sync(0xffffffffu,
                                                lane < KNN && ent < pns);
                    int pos = __popc(pm);
                    unsigned long long up = __shfl_up_sync(0xffffffffu, ent, 1);
                    unsigned long long ne = (lane == pos) ? pns
                                            : (lane > pos ? up : ent);
                    if (lane < KNN) sList[r * KNN + lane] = ne;
                    if (lane == KNN - 1) sThr[r] = ne;
                    __syncwarp();
                }
            }
        }
        __syncthreads();
    }

    // ---- write results ----
#pragma unroll 1
    for (int rr = 0; rr < 8; rr++) {
        int r = w * 8 + rr;
        if (lane < KNN) {
            int grow = b * N_PTS + bi * 64 + r;
            g_idx[grow * KNN + lane] = (int)(sList[r * KNN + lane] & 0xFFFFFFFFULL);
        }
    }
}

// -------- K4a: fold decoder+residual weights (BN scale) into g_Wt -----------
__global__ void k_fold(const float* __restrict__ Wdec, const float* __restrict__ gdec,
                       const float* __restrict__ bdec, const float* __restrict__ mdec,
                       const float* __restrict__ vdec,
                       const float* __restrict__ Wres, const float* __restrict__ gres,
                       const float* __restrict__ bres, const float* __restrict__ mres,
                       const float* __restrict__ vres)
{
    int tid = blockIdx.x * blockDim.x + threadIdx.x;
    for (int e = tid; e < 160 * 128; e += gridDim.x * blockDim.x) {
        int k = e >> 7, o = e & 127;
        float wv;
        if (k < 96) wv = Wdec[o * 96 + k] * (gdec[o] * rsqrtf(vdec[o] + EPSBN));
        else        wv = Wres[o * 64 + (k - 96)] * (gres[o] * rsqrtf(vres[o] + EPSBN));
        g_Wt[e] = wv;
    }
    if (tid < 128) {
        float sd = gdec[tid] * rsqrtf(vdec[tid] + EPSBN);
        g_bias[tid] = bdec[tid] - mdec[tid] * sd;
        float sr = gres[tid] * rsqrtf(vres[tid] + EPSBN);
        g_bias[128 + tid] = bres[tid] - mres[tid] * sr;
    }
}

// -------- K4b: GCN branches + gmax, one warp per point ----------------------
__global__ void __launch_bounds__(256) k_gcn(
    const float* __restrict__ Wg1, const float* __restrict__ gg1,
    const float* __restrict__ bg1, const float* __restrict__ mg1,
    const float* __restrict__ vg1,
    const float* __restrict__ Wg2, const float* __restrict__ gg2,
    const float* __restrict__ bg2, const float* __restrict__ mg2,
    const float* __restrict__ vg2)
{
    __shared__ float sW1[32 * 33], sW2[32 * 33];
    __shared__ float sS1[32], sS2[32], t1[32], t2[32];
    __shared__ float sNb[8][KNN * 16];
    __shared__ float sCtr[8][16];

    int tid = threadIdx.x, lane = tid & 31, w = tid >> 5;

    if (tid < 32) {
        float s = gg1[tid] * rsqrtf(vg1[tid] + EPSBN);
        sS1[tid] = s; t1[tid] = bg1[tid] - mg1[tid] * s;
        s = gg2[tid] * rsqrtf(vg2[tid] + EPSBN);
        sS2[tid] = s; t2[tid] = bg2[tid] - mg2[tid] * s;
    }
    __syncthreads();
    for (int e = tid; e < 1024; e += 256) {
        int o = e >> 5, c = e & 31;
        sW1[o * 33 + c] = Wg1[e] * sS1[o];
        sW2[o * 33 + c] = Wg2[e] * sS2[o];
    }
    __syncthreads();

    int pt = blockIdx.x * 8 + w;                    // 0 .. B*N-1
    int b = pt >> 12;
    int idxv = (lane < KNN) ? g_idx[pt * KNN + lane] : 0;
    if (lane < 4)
        *(float4*)&sCtr[w][lane * 4] = *(const float4*)&g_hb[(size_t)pt * C_BOT + lane * 4];
#pragma unroll
    for (int t = 0; t < 3; t++) {                   // 80 float4 gathers
        int e = lane + t * 32;
        int row = (e < 80) ? (e >> 2) : 0;
        int ni = __shfl_sync(0xffffffffu, idxv, row);
        if (e < 80) {
            int q = e & 3;
            float4 v = *(const float4*)&g_hb[((size_t)(b << 12) + ni) * C_BOT + q * 4];
            *(float4*)&sNb[w][row * 16 + q * 4] = v;
        }
    }
    __syncwarp();

    float ctr[16];
#pragma unroll
    for (int c = 0; c < 16; c++) ctr[c] = sCtr[w][c];

    float cd1 = t1[lane], cd2 = t2[lane];
#pragma unroll
    for (int c = 0; c < 16; c++) {
        cd1 += sW1[lane * 33 + 16 + c] * ctr[c];
        cd2 += sW2[lane * 33 + 16 + c] * ctr[c];
    }
    float m1 = -FLT_MAX, m2 = -FLT_MAX;
#pragma unroll
    for (int k = 0; k < KNN; k++) {
        float a = cd1;
#pragma unroll
        for (int c = 0; c < 16; c++) a += sW1[lane * 33 + c] * sNb[w][k * 16 + c];
        a = a > 0.f ? a : 0.2f * a;
        m1 = fmaxf(m1, a);
        if ((k & 1) == 0) {
            float a2 = cd2;
#pragma unroll
            for (int c = 0; c < 16; c++) a2 += sW2[lane * 33 + c] * sNb[w][k * 16 + c];
            a2 = a2 > 0.f ? a2 : 0.2f * a2;
            m2 = fmaxf(m2, a2);
        }
    }
    float gm;
    if (lane < 16) {
        gm = -FLT_MAX;
#pragma unroll
        for (int k = 0; k < KNN; k++) gm = fmaxf(gm, sNb[w][k * 16 + lane]);
    } else {
        gm = ctr[lane - 16];
    }
    float* ap = g_allf + (size_t)pt * 96;
    ap[lane] = m1; ap[32 + lane] = m2; ap[64 + lane] = gm;
}

// -------- K4c: decoder+residual GEMM, 128o x 64n tiles ----------------------
#define FPAD 68
__global__ void __launch_bounds__(256) k_dec(const float* __restrict__ x,
                                             float* __restrict__ out)
{
    extern __shared__ float sm[];
    float* sW = sm;                     // 160*128
    float* sF = sW + 160 * 128;         // 16*FPAD
    float* sB = sF + 16 * FPAD;         // 256

    int tid = threadIdx.x;
    int b = blockIdx.y, n0 = blockIdx.x * 64;
    size_t gr0 = (size_t)b * N_PTS + n0;

    for (int e = tid; e < 160 * 128 / 4; e += 256)
        ((float4*)sW)[e] = ((const float4*)g_Wt)[e];
    sB[tid] = g_bias[tid];      // 256 threads cover 256
    __syncthreads();

    int to = tid & 31, tn = tid >> 5;   // o tile of 4, n tile of 8
    float acc[4][8];
    float res[4][8];

    // ---- phase 1: decoder, K=96 from allf ----
#pragma unroll
    for (int i = 0; i < 4; i++)
#pragma unroll
        for (int j = 0; j < 8; j++) acc[i][j] = 0.f;

    for (int kc = 0; kc < 6; kc++) {
        {
            int row = tid >> 2, q = tid & 3;
            float4 v = *(const float4*)&g_allf[(gr0 + row) * 96 + kc * 16 + q * 4];
            sF[(q * 4 + 0) * FPAD + row] = v.x;
            sF[(q * 4 + 1) * FPAD + row] = v.y;
            sF[(q * 4 + 2) * FPAD + row] = v.z;
            sF[(q * 4 + 3) * FPAD + row] = v.w;
        }
        __syncthreads();
#pragma unroll
        for (int k = 0; k < 16; k++) {
            float4 wv = *(float4*)&sW[(kc * 16 + k) * 128 + to * 4];
            float4 f0 = *(float4*)&sF[k * FPAD + tn * 8];
            float4 f1 = *(float4*)&sF[k * FPAD + tn * 8 + 4];
            float wr[4] = {wv.x, wv.y, wv.z, wv.w};
            float fr[8] = {f0.x, f0.y, f0.z, f0.w, f1.x, f1.y, f1.z, f1.w};
#pragma unroll
            for (int i = 0; i < 4; i++)
#pragma unroll
                for (int j = 0; j < 8; j++) acc[i][j] += wr[i] * fr[j];
        }
        __syncthreads();
    }
#pragma unroll
    for (int i = 0; i < 4; i++) {
        float bv = sB[to * 4 + i];
#pragma unroll
        for (int j = 0; j < 8; j++) {
            res[i][j] = fmaxf(acc[i][j] + bv, 0.f);
            acc[i][j] = 0.f;
        }
    }

    // ---- phase 2: residual, K=64 from x (coalesced channel rows) ----
    for (int kc = 0; kc < 4; kc++) {
        {
            int c = tid >> 4, nq = tid & 15;
            float4 v = *(const float4*)&x[((size_t)(b * C_IN + kc * 16 + c)) * N_PTS +
                                          n0 + nq * 4];
            *(float4*)&sF[c * FPAD + nq * 4] = v;
        }
        __syncthreads();
#pragma unroll
        for (int k = 0; k < 16; k++) {
            float4 wv = *(float4*)&sW[(96 + kc * 16 + k) * 128 + to * 4];
            float4 f0 = *(float4*)&sF[k * FPAD + tn * 8];
            float4 f1 = *(float4*)&sF[k * FPAD + tn * 8 + 4];
            float wr[4] = {wv.x, wv.y, wv.z, wv.w};
            float fr[8] = {f0.x, f0.y, f0.z, f0.w, f1.x, f1.y, f1.z, f1.w};
#pragma unroll
            for (int i = 0; i < 4; i++)
#pragma unroll
                for (int j = 0; j < 8; j++) acc[i][j] += wr[i] * fr[j];
        }
        __syncthreads();
    }

#pragma unroll
    for (int i = 0; i < 4; i++) {
        int o = to * 4 + i;
        float bv = sB[128 + o];
        float4 r0, r1;
        r0.x = res[i][0] + fmaxf(acc[i][0] + bv, 0.f);
        r0.y = res[i][1] + fmaxf(acc[i][1] + bv, 0.f);
        r0.z = res[i][2] + fmaxf(acc[i][2] + bv, 0.f);
        r0.w = res[i][3] + fmaxf(acc[i][3] + bv, 0.f);
        r1.x = res[i][4] + fmaxf(acc[i][4] + bv, 0.f);
        r1.y = res[i][5] + fmaxf(acc[i][5] + bv, 0.f);
        r1.z = res[i][6] + fmaxf(acc[i][6] + bv, 0.f);
        r1.w = res[i][7] + fmaxf(acc[i][7] + bv, 0.f);
        float* op = out + ((size_t)(b * C_OUT + o)) * N_PTS + n0 + tn * 8;
        *(float4*)op = r0;
        *(float4*)(op + 4) = r1;
    }
}

// ---------------- launch -----------------------------------------------------
extern "C" void kernel_launch(void* const* d_in, const int* in_sizes, int n_in,
                              void* d_out, int out_size)
{
    const float* x    = (const float*)d_in[0];
    const float* Wres = (const float*)d_in[1];
    const float* gres = (const float*)d_in[2];
    const float* bres = (const float*)d_in[3];
    const float* mres = (const float*)d_in[4];
    const float* vres = (const float*)d_in[5];
    const float* Wbot = (const float*)d_in[6];
    const float* gbot = (const float*)d_in[7];
    const float* bbot = (const float*)d_in[8];
    const float* mbot = (const float*)d_in[9];
    const float* vbot = (const float*)d_in[10];
    const float* Wg1  = (const float*)d_in[11];
    const float* gg1  = (const float*)d_in[12];
    const float* bg1  = (const float*)d_in[13];
    const float* mg1  = (const float*)d_in[14];
    const float* vg1  = (const float*)d_in[15];
    const float* Wg2  = (const float*)d_in[16];
    const float* gg2  = (const float*)d_in[17];
    const float* bg2  = (const float*)d_in[18];
    const float* mg2  = (const float*)d_in[19];
    const float* vg2  = (const float*)d_in[20];
    const float* Wdec = (const float*)d_in[21];
    const float* gdec = (const float*)d_in[22];
    const float* bdec = (const float*)d_in[23];
    const float* mdec = (const float*)d_in[24];
    const float* vdec = (const float*)d_in[25];
    float* out = (float*)d_out;

    size_t smem_fused = (64 * KNN + 64) * sizeof(unsigned long long) +
                        (64 * 64 * 2 + 64 * 68 + 128) * sizeof(float);
    cudaFuncSetAttribute(k_fused, cudaFuncAttributeMaxDynamicSharedMemorySize,
                         (int)smem_fused);
    size_t smem_dec = (160 * 128 + 16 * FPAD + 256) * sizeof(float);
    cudaFuncSetAttribute(k_dec, cudaFuncAttributeMaxDynamicSharedMemorySize,
                         (int)smem_dec);

    k_prep<<<(BATCH * N_PTS + 255) / 256, 256>>>(x, Wbot, gbot, bbot, mbot, vbot);
    k_fold<<<80, 256>>>(Wdec, gdec, bdec, mdec, vdec, Wres, gres, bres, mres, vres);
    k_fused<<<dim3(N_PTS / 64, BATCH), 256, smem_fused>>>(x);
    k_gcn<<<BATCH * N_PTS / 8, 256>>>(Wg1, gg1, bg1, mg1, vg1,
                                      Wg2, gg2, bg2, mg2, vg2);
    k_dec<<<dim3(N_PTS / 64, BATCH), 256, smem_dec>>>(x, out);
}

// round 8
// speedup vs baseline: 1.5954x; 1.5954x over previous
#include <cuda_runtime.h>
#include <math.h>
#include <float.h>

#define N_PTS 4096
#define BATCH 4
#define C_IN  64
#define C_OUT 128
#define KNN   20
#define C_BOT 16
#define EPSBN 1e-5f

// ---------------- scratch (device globals; no allocation) ----------------
__device__ float g_sq[BATCH * N_PTS];                       // 64 KB
__device__ float g_hb[BATCH * N_PTS * C_BOT];               // 1 MB, [B*N,16]
__device__ float g_d2[(size_t)BATCH * N_PTS * N_PTS];       // 256 MiB
__device__ int   g_idx[BATCH * N_PTS * KNN];                // 1.3 MB
__device__ float g_allf[(size_t)BATCH * N_PTS * 96];        // 25 MB, [B*N,96]
__device__ float g_Wt[160 * 128];                           // folded [k][o]
__device__ float g_bias[256];                               // tDec[128], tRes[128]

// ---------------- f32x2 helpers (Blackwell packed FMA path) -----------------
__device__ __forceinline__ unsigned long long pk2(float x, float y) {
    unsigned long long r;
    asm("mov.b64 %0, {%1,%2};" : "=l"(r) : "f"(x), "f"(y));
    return r;
}
__device__ __forceinline__ void upk2(unsigned long long v, float& x, float& y) {
    asm("mov.b64 {%0,%1}, %2;" : "=f"(x), "=f"(y) : "l"(v));
}
__device__ __forceinline__ unsigned long long fma2(unsigned long long a,
                                                   unsigned long long b,
                                                   unsigned long long c) {
    unsigned long long d;
    asm("fma.rn.f32x2 %0, %1, %2, %3;" : "=l"(d) : "l"(a), "l"(b), "l"(c));
    return d;
}
__device__ __forceinline__ unsigned okey(float f) {
    unsigned u = __float_as_uint(f);
    return u ^ (unsigned)(((int)u >> 31) | 0x80000000);
}

// ---------------- K1: sq norms + bottleneck conv (BN+ReLU), hb transposed ----
__global__ void k_prep(const float* __restrict__ x,
                       const float* __restrict__ Wb, const float* __restrict__ gb,
                       const float* __restrict__ bb, const float* __restrict__ mb,
                       const float* __restrict__ vb)
{
    __shared__ float sW[C_BOT][C_IN];
    __shared__ float sS[C_BOT], sT[C_BOT];
    int tid = threadIdx.x;
    if (tid < C_BOT) {
        float s = gb[tid] * rsqrtf(vb[tid] + EPSBN);
        sS[tid] = s;
        sT[tid] = bb[tid] - mb[tid] * s;
    }
    for (int e = tid; e < C_BOT * C_IN; e += blockDim.x)
        sW[e >> 6][e & 63] = Wb[e];
    __syncthreads();

    int g = blockIdx.x * blockDim.x + tid;      // 0 .. BATCH*N_PTS-1
    if (g >= BATCH * N_PTS) return;
    int b = g >> 12, n = g & (N_PTS - 1);
    const float* xp = x + (size_t)b * C_IN * N_PTS + n;

    float xc[C_IN];
    float sq = 0.f;
#pragma unroll
    for (int c = 0; c < C_IN; c++) {
        float v = xp[(size_t)c * N_PTS];
        xc[c] = v;
        sq += v * v;                 // same ascending-c order as GEMM dot
    }
    g_sq[g] = sq;

#pragma unroll
    for (int o = 0; o < C_BOT; o++) {
        float acc = 0.f;
#pragma unroll
        for (int c = 0; c < C_IN; c++) acc += sW[o][c] * xc[c];
        float h = acc * sS[o] + sT[o];
        g_hb[(size_t)g * C_BOT + o] = fmaxf(h, 0.f);
    }
}

// ------- K2: pairwise squared distances, 128x128 tile, 8x8/thread f32x2 -----
__global__ void __launch_bounds__(256) k_dist(const float* __restrict__ x)
{
    extern __shared__ float smd[];
    float* As  = smd;                  // 64*128
    float* Bs  = As + 64 * 128;        // 64*128
    float* sqA = Bs + 64 * 128;        // 128
    float* sqB = sqA + 128;            // 128

    int b  = blockIdx.z;
    int bi = blockIdx.y;
    int bj = blockIdx.x;
    int tid = threadIdx.x;
    const float* xb = x + (size_t)b * C_IN * N_PTS;

    for (int e = tid; e < 64 * 32; e += 256) {
        int k = e >> 5, i = e & 31;
        ((float4*)As)[k * 32 + i] =
            *(const float4*)&xb[(size_t)k * N_PTS + bi * 128 + i * 4];
        ((float4*)Bs)[k * 32 + i] =
            *(const float4*)&xb[(size_t)k * N_PTS + bj * 128 + i * 4];
    }
    if (tid < 128)      sqA[tid]       = g_sq[b * N_PTS + bi * 128 + tid];
    else                sqB[tid - 128] = g_sq[b * N_PTS + bj * 128 + (tid - 128)];
    __syncthreads();

    int tx = tid & 15, ty = tid >> 4;
    const float4* As4 = (const float4*)As;
    const unsigned long long* Bs8 = (const unsigned long long*)Bs;

    unsigned long long acc2[8][4];
#pragma unroll
    for (int i = 0; i < 8; i++)
#pragma unroll
        for (int j = 0; j < 4; j++) acc2[i][j] = 0ULL;

#pragma unroll 2
    for (int k = 0; k < 64; k++) {
        float4 a0 = As4[k * 32 + ty * 2];
        float4 a1 = As4[k * 32 + ty * 2 + 1];
        unsigned long long B0 = Bs8[k * 64 + tx * 4 + 0];
        unsigned long long B1 = Bs8[k * 64 + tx * 4 + 1];
        unsigned long long B2 = Bs8[k * 64 + tx * 4 + 2];
        unsigned long long B3 = Bs8[k * 64 + tx * 4 + 3];
        unsigned long long A[8];
        A[0] = pk2(a0.x, a0.x); A[1] = pk2(a0.y, a0.y);
        A[2] = pk2(a0.z, a0.z); A[3] = pk2(a0.w, a0.w);
        A[4] = pk2(a1.x, a1.x); A[5] = pk2(a1.y, a1.y);
        A[6] = pk2(a1.z, a1.z); A[7] = pk2(a1.w, a1.w);
#pragma unroll
        for (int i = 0; i < 8; i++) {
            acc2[i][0] = fma2(A[i], B0, acc2[i][0]);
            acc2[i][1] = fma2(A[i], B1, acc2[i][1]);
            acc2[i][2] = fma2(A[i], B2, acc2[i][2]);
            acc2[i][3] = fma2(A[i], B3, acc2[i][3]);
        }
    }

#pragma unroll
    for (int ri = 0; ri < 8; ri++) {
        int r = ty * 8 + ri;
        float sr = sqA[r];
        float c0, c1;
        float4 v0, v1;
        upk2(acc2[ri][0], c0, c1);
        v0.x = sr + sqB[tx * 8 + 0] - 2.f * c0;
        v0.y = sr + sqB[tx * 8 + 1] - 2.f * c1;
        upk2(acc2[ri][1], c0, c1);
        v0.z = sr + sqB[tx * 8 + 2] - 2.f * c0;
        v0.w = sr + sqB[tx * 8 + 3] - 2.f * c1;
        upk2(acc2[ri][2], c0, c1);
        v1.x = sr + sqB[tx * 8 + 4] - 2.f * c0;
        v1.y = sr + sqB[tx * 8 + 5] - 2.f * c1;
        upk2(acc2[ri][3], c0, c1);
        v1.z = sr + sqB[tx * 8 + 6] - 2.f * c0;
        v1.w = sr + sqB[tx * 8 + 7] - 2.f * c1;
        float* dp = g_d2 + ((size_t)(b * N_PTS + bi * 128 + r)) * N_PTS +
                    bj * 128 + tx * 8;
        *(float4*)dp = v0;
        *(float4*)(dp + 4) = v1;
    }
}

// -------- K3: streaming top-K, one warp per row, float4 chunks --------------
__global__ void __launch_bounds__(256) k_topk()
{
    int lane = threadIdx.x & 31, w = threadIdx.x >> 5;
    int row = blockIdx.x * 8 + w;              // b*N + n
    const float* dp = g_d2 + (size_t)row * N_PTS;

    // ---- init: elements 0..31, bitonic sort ascending ----
    unsigned u0 = okey(dp[lane]);
    unsigned long long p = ((unsigned long long)u0 << 32) | (unsigned)lane;
#pragma unroll
    for (int k2 = 2; k2 <= 32; k2 <<= 1) {
#pragma unroll
        for (int j = k2 >> 1; j > 0; j >>= 1) {
            unsigned long long q = __shfl_xor_sync(0xffffffffu, p, j);
            bool up = ((lane & k2) == 0);
            bool lower = ((lane & j) == 0);
            bool takeMin = (up == lower);
            bool qs = q < p;
            p = (takeMin == qs) ? q : p;
        }
    }
    unsigned long long thr = __shfl_sync(0xffffffffu, p, KNN - 1);

    // ---- stream chunks of 128 (covers 0..4095; chunk0 masks idx<32) ----
#pragma unroll 1
    for (int c = 0; c < 32; c++) {
        float4 v = ((const float4*)dp)[c * 32 + lane];
        unsigned base = (unsigned)(c * 128 + lane * 4);
        unsigned long long p0 = ((unsigned long long)okey(v.x) << 32) | base;
        unsigned long long p1 = ((unsigned long long)okey(v.y) << 32) | (base + 1);
        unsigned long long p2 = ((unsigned long long)okey(v.z) << 32) | (base + 2);
        unsigned long long p3 = ((unsigned long long)okey(v.w) << 32) | (base + 3);
        if (c == 0 && lane < 8) { p0 = ~0ULL; p1 = ~0ULL; p2 = ~0ULL; p3 = ~0ULL; }
        unsigned long long mn01 = p0 < p1 ? p0 : p1;
        unsigned long long mn23 = p2 < p3 ? p2 : p3;
        unsigned long long mn = mn01 < mn23 ? mn01 : mn23;
        unsigned hit = __ballot_sync(0xffffffffu, mn < thr);
        while (hit) {
            int src = __ffs(hit) - 1;
            hit &= hit - 1;
            unsigned long long c0 = __shfl_sync(0xffffffffu, p0, src);
            unsigned long long c1 = __shfl_sync(0xffffffffu, p1, src);
            unsigned long long c2 = __shfl_sync(0xffffffffu, p2, src);
            unsigned long long c3 = __shfl_sync(0xffffffffu, p3, src);
#pragma unroll
            for (int q = 0; q < 4; q++) {
                unsigned long long cand = (q == 0) ? c0 : (q == 1) ? c1
                                          : (q == 2) ? c2 : c3;
                if (cand < thr) {      // uniform branch (cand, thr warp-uniform)
                    unsigned pm = __ballot_sync(0xffffffffu, p < cand);
                    int pos = __popc(pm);
                    unsigned long long up = __shfl_up_sync(0xffffffffu, p, 1);
                    if (lane == pos)      p = cand;
                    else if (lane > pos)  p = up;
                    thr = __shfl_sync(0xffffffffu, p, KNN - 1);
                }
            }
        }
    }

    if (lane < KNN)
        g_idx[row * KNN + lane] = (int)(p & 0xFFFFFFFFULL);
}

// -------- K4a: fold decoder+residual weights (BN scale) into g_Wt -----------
__global__ void k_fold(const float* __restrict__ Wdec, const float* __restrict__ gdec,
                       const float* __restrict__ bdec, const float* __restrict__ mdec,
                       const float* __restrict__ vdec,
                       const float* __restrict__ Wres, const float* __restrict__ gres,
                       const float* __restrict__ bres, const float* __restrict__ mres,
                       const float* __restrict__ vres)
{
    int tid = blockIdx.x * blockDim.x + threadIdx.x;
    for (int e = tid; e < 160 * 128; e += gridDim.x * blockDim.x) {
        int k = e >> 7, o = e & 127;
        float wv;
        if (k < 96) wv = Wdec[o * 96 + k] * (gdec[o] * rsqrtf(vdec[o] + EPSBN));
        else        wv = Wres[o * 64 + (k - 96)] * (gres[o] * rsqrtf(vres[o] + EPSBN));
        g_Wt[e] = wv;
    }
    if (tid < 128) {
        float sd = gdec[tid] * rsqrtf(vdec[tid] + EPSBN);
        g_bias[tid] = bdec[tid] - mdec[tid] * sd;
        float sr = gres[tid] * rsqrtf(vres[tid] + EPSBN);
        g_bias[128 + tid] = bres[tid] - mres[tid] * sr;
    }
}

// -------- K4b: GCN branches + gmax, one warp per point ----------------------
__global__ void __launch_bounds__(256) k_gcn(
    const float* __restrict__ Wg1, const float* __restrict__ gg1,
    const float* __restrict__ bg1, const float* __restrict__ mg1,
    const float* __restrict__ vg1,
    const float* __restrict__ Wg2, const float* __restrict__ gg2,
    const float* __restrict__ bg2, const float* __restrict__ mg2,
    const float* __restrict__ vg2)
{
    __shared__ float sW1[32 * 33], sW2[32 * 33];
    __shared__ float sS1[32], sS2[32], t1[32], t2[32];
    __shared__ float sNb[8][KNN * 16];
    __shared__ float sCtr[8][16];

    int tid = threadIdx.x, lane = tid & 31, w = tid >> 5;

    if (tid < 32) {
        float s = gg1[tid] * rsqrtf(vg1[tid] + EPSBN);
        sS1[tid] = s; t1[tid] = bg1[tid] - mg1[tid] * s;
        s = gg2[tid] * rsqrtf(vg2[tid] + EPSBN);
        sS2[tid] = s; t2[tid] = bg2[tid] - mg2[tid] * s;
    }
    __syncthreads();
    for (int e = tid; e < 1024; e += 256) {
        int o = e >> 5, c = e & 31;
        sW1[o * 33 + c] = Wg1[e] * sS1[o];
        sW2[o * 33 + c] = Wg2[e] * sS2[o];
    }
    __syncthreads();

    int pt = blockIdx.x * 8 + w;                    // 0 .. B*N-1
    int b = pt >> 12;
    int idxv = (lane < KNN) ? g_idx[pt * KNN + lane] : 0;
    if (lane < 4)
        *(float4*)&sCtr[w][lane * 4] = *(const float4*)&g_hb[(size_t)pt * C_BOT + lane * 4];
#pragma unroll
    for (int t = 0; t < 3; t++) {                   // 80 float4 gathers
        int e = lane + t * 32;
        int row = (e < 80) ? (e >> 2) : 0;
        int ni = __shfl_sync(0xffffffffu, idxv, row);
        if (e < 80) {
            int q = e & 3;
            float4 v = *(const float4*)&g_hb[((size_t)(b << 12) + ni) * C_BOT + q * 4];
            *(float4*)&sNb[w][row * 16 + q * 4] = v;
        }
    }
    __syncwarp();

    float ctr[16];
#pragma unroll
    for (int c = 0; c < 16; c++) ctr[c] = sCtr[w][c];

    float cd1 = t1[lane], cd2 = t2[lane];
#pragma unroll
    for (int c = 0; c < 16; c++) {
        cd1 += sW1[lane * 33 + 16 + c] * ctr[c];
        cd2 += sW2[lane * 33 + 16 + c] * ctr[c];
    }
    float m1 = -FLT_MAX, m2 = -FLT_MAX;
#pragma unroll
    for (int k = 0; k < KNN; k++) {
        float a = cd1;
#pragma unroll
        for (int c = 0; c < 16; c++) a += sW1[lane * 33 + c] * sNb[w][k * 16 + c];
        a = a > 0.f ? a : 0.2f * a;
        m1 = fmaxf(m1, a);
        if ((k & 1) == 0) {
            float a2 = cd2;
#pragma unroll
            for (int c = 0; c < 16; c++) a2 += sW2[lane * 33 + c] * sNb[w][k * 16 + c];
            a2 = a2 > 0.f ? a2 : 0.2f * a2;
            m2 = fmaxf(m2, a2);
        }
    }
    float gm;
    if (lane < 16) {
        gm = -FLT_MAX;
#pragma unroll
        for (int k = 0; k < KNN; k++) gm = fmaxf(gm, sNb[w][k * 16 + lane]);
    } else {
        gm = ctr[lane - 16];
    }
    float* ap = g_allf + (size_t)pt * 96;
    ap[lane] = m1; ap[32 + lane] = m2; ap[64 + lane] = gm;
}

// -------- K4c: decoder+residual GEMM, 128o x 64n tiles ----------------------
#define FPAD 68
__global__ void __launch_bounds__(256) k_dec(const float* __restrict__ x,
                                             float* __restrict__ out)
{
    extern __shared__ float sm[];
    float* sW = sm;                     // 160*128
    float* sF = sW + 160 * 128;         // 16*FPAD
    float* sB = sF + 16 * FPAD;         // 256

    int tid = threadIdx.x;
    int b = blockIdx.y, n0 = blockIdx.x * 64;
    size_t gr0 = (size_t)b * N_PTS + n0;

    for (int e = tid; e < 160 * 128 / 4; e += 256)
        ((float4*)sW)[e] = ((const float4*)g_Wt)[e];
    sB[tid] = g_bias[tid];      // 256 threads cover 256
    __syncthreads();

    int to = tid & 31, tn = tid >> 5;   // o tile of 4, n tile of 8
    float acc[4][8];
    float res[4][8];

    // ---- phase 1: decoder, K=96 from allf ----
#pragma unroll
    for (int i = 0; i < 4; i++)
#pragma unroll
        for (int j = 0; j < 8; j++) acc[i][j] = 0.f;

    for (int kc = 0; kc < 6; kc++) {
        {
            int row = tid >> 2, q = tid & 3;
            float4 v = *(const float4*)&g_allf[(gr0 + row) * 96 + kc * 16 + q * 4];
            sF[(q * 4 + 0) * FPAD + row] = v.x;
            sF[(q * 4 + 1) * FPAD + row] = v.y;
            sF[(q * 4 + 2) * FPAD + row] = v.z;
            sF[(q * 4 + 3) * FPAD + row] = v.w;
        }
        __syncthreads();
#pragma unroll
        for (int k = 0; k < 16; k++) {
            float4 wv = *(float4*)&sW[(kc * 16 + k) * 128 + to * 4];
            float4 f0 = *(float4*)&sF[k * FPAD + tn * 8];
            float4 f1 = *(float4*)&sF[k * FPAD + tn * 8 + 4];
            float wr[4] = {wv.x, wv.y, wv.z, wv.w};
            float fr[8] = {f0.x, f0.y, f0.z, f0.w, f1.x, f1.y, f1.z, f1.w};
#pragma unroll
            for (int i = 0; i < 4; i++)
#pragma unroll
                for (int j = 0; j < 8; j++) acc[i][j] += wr[i] * fr[j];
        }
        __syncthreads();
    }
#pragma unroll
    for (int i = 0; i < 4; i++) {
        float bv = sB[to * 4 + i];
#pragma unroll
        for (int j = 0; j < 8; j++) {
            res[i][j] = fmaxf(acc[i][j] + bv, 0.f);
            acc[i][j] = 0.f;
        }
    }

    // ---- phase 2: residual, K=64 from x (coalesced channel rows) ----
    for (int kc = 0; kc < 4; kc++) {
        {
            int c = tid >> 4, nq = tid & 15;
            float4 v = *(const float4*)&x[((size_t)(b * C_IN + kc * 16 + c)) * N_PTS +
                                          n0 + nq * 4];
            *(float4*)&sF[c * FPAD + nq * 4] = v;
        }
        __syncthreads();
#pragma unroll
        for (int k = 0; k < 16; k++) {
            float4 wv = *(float4*)&sW[(96 + kc * 16 + k) * 128 + to * 4];
            float4 f0 = *(float4*)&sF[k * FPAD + tn * 8];
            float4 f1 = *(float4*)&sF[k * FPAD + tn * 8 + 4];
            float wr[4] = {wv.x, wv.y, wv.z, wv.w};
            float fr[8] = {f0.x, f0.y, f0.z, f0.w, f1.x, f1.y, f1.z, f1.w};
#pragma unroll
            for (int i = 0; i < 4; i++)
#pragma unroll
                for (int j = 0; j < 8; j++) acc[i][j] += wr[i] * fr[j];
        }
        __syncthreads();
    }

#pragma unroll
    for (int i = 0; i < 4; i++) {
        int o = to * 4 + i;
        float bv = sB[128 + o];
        float4 r0, r1;
        r0.x = res[i][0] + fmaxf(acc[i][0] + bv, 0.f);
        r0.y = res[i][1] + fmaxf(acc[i][1] + bv, 0.f);
        r0.z = res[i][2] + fmaxf(acc[i][2] + bv, 0.f);
        r0.w = res[i][3] + fmaxf(acc[i][3] + bv, 0.f);
        r1.x = res[i][4] + fmaxf(acc[i][4] + bv, 0.f);
        r1.y = res[i][5] + fmaxf(acc[i][5] + bv, 0.f);
        r1.z = res[i][6] + fmaxf(acc[i][6] + bv, 0.f);
        r1.w = res[i][7] + fmaxf(acc[i][7] + bv, 0.f);
        float* op = out + ((size_t)(b * C_OUT + o)) * N_PTS + n0 + tn * 8;
        *(float4*)op = r0;
        *(float4*)(op + 4) = r1;
    }
}

// ---------------- launch -----------------------------------------------------
extern "C" void kernel_launch(void* const* d_in, const int* in_sizes, int n_in,
                              void* d_out, int out_size)
{
    const float* x    = (const float*)d_in[0];
    const float* Wres = (const float*)d_in[1];
    const float* gres = (const float*)d_in[2];
    const float* bres = (const float*)d_in[3];
    const float* mres = (const float*)d_in[4];
    const float* vres = (const float*)d_in[5];
    const float* Wbot = (const float*)d_in[6];
    const float* gbot = (const float*)d_in[7];
    const float* bbot = (const float*)d_in[8];
    const float* mbot = (const float*)d_in[9];
    const float* vbot = (const float*)d_in[10];
    const float* Wg1  = (const float*)d_in[11];
    const float* gg1  = (const float*)d_in[12];
    const float* bg1  = (const float*)d_in[13];
    const float* mg1  = (const float*)d_in[14];
    const float* vg1  = (const float*)d_in[15];
    const float* Wg2  = (const float*)d_in[16];
    const float* gg2  = (const float*)d_in[17];
    const float* bg2  = (const float*)d_in[18];
    const float* mg2  = (const float*)d_in[19];
    const float* vg2  = (const float*)d_in[20];
    const float* Wdec = (const float*)d_in[21];
    const float* gdec = (const float*)d_in[22];
    const float* bdec = (const float*)d_in[23];
    const float* mdec = (const float*)d_in[24];
    const float* vdec = (const float*)d_in[25];
    float* out = (float*)d_out;

    size_t smem_dist = (64 * 128 * 2 + 256) * sizeof(float);
    cudaFuncSetAttribute(k_dist, cudaFuncAttributeMaxDynamicSharedMemorySize,
                         (int)smem_dist);
    size_t smem_dec = (160 * 128 + 16 * FPAD + 256) * sizeof(float);
    cudaFuncSetAttribute(k_dec, cudaFuncAttributeMaxDynamicSharedMemorySize,
                         (int)smem_dec);

    k_prep<<<(BATCH * N_PTS + 255) / 256, 256>>>(x, Wbot, gbot, bbot, mbot, vbot);
    k_fold<<<80, 256>>>(Wdec, gdec, bdec, mdec, vdec, Wres, gres, bres, mres, vres);
    k_dist<<<dim3(N_PTS / 128, N_PTS / 128, BATCH), 256, smem_dist>>>(x);
    k_topk<<<BATCH * N_PTS / 8, 256>>>();
    k_gcn<<<BATCH * N_PTS / 8, 256>>>(Wg1, gg1, bg1, mg1, vg1,
                                      Wg2, gg2, bg2, mg2, vg2);
    k_dec<<<dim3(N_PTS / 64, BATCH), 256, smem_dec>>>(x, out);
}

// round 9
// speedup vs baseline: 1.6123x; 1.0106x over previous
#include <cuda_runtime.h>
#include <math.h>
#include <float.h>

#define N_PTS 4096
#define BATCH 4
#define C_IN  64
#define C_OUT 128
#define KNN   20
#define C_BOT 16
#define EPSBN 1e-5f

// ---------------- scratch (device globals; no allocation) ----------------
__device__ float g_sq[BATCH * N_PTS];                       // 64 KB
__device__ float g_hb[BATCH * N_PTS * C_BOT];               // 1 MB, [B*N,16]
__device__ float g_d2[(size_t)BATCH * N_PTS * N_PTS];       // 256 MiB
__device__ int   g_idx[BATCH * N_PTS * KNN];                // 1.3 MB
__device__ float g_allf[(size_t)BATCH * N_PTS * 96];        // 25 MB, [B*N,96]
__device__ float g_Wt[160 * 128];                           // folded [k][o]
__device__ float g_bias[256];                               // tDec[128], tRes[128]

// ---------------- f32x2 helpers (Blackwell packed FMA path) -----------------
__device__ __forceinline__ unsigned long long pk2(float x, float y) {
    unsigned long long r;
    asm("mov.b64 %0, {%1,%2};" : "=l"(r) : "f"(x), "f"(y));
    return r;
}
__device__ __forceinline__ void upk2(unsigned long long v, float& x, float& y) {
    asm("mov.b64 {%0,%1}, %2;" : "=f"(x), "=f"(y) : "l"(v));
}
__device__ __forceinline__ unsigned long long fma2(unsigned long long a,
                                                   unsigned long long b,
                                                   unsigned long long c) {
    unsigned long long d;
    asm("fma.rn.f32x2 %0, %1, %2, %3;" : "=l"(d) : "l"(a), "l"(b), "l"(c));
    return d;
}
__device__ __forceinline__ unsigned okey(float f) {
    unsigned u = __float_as_uint(f);
    return u ^ (unsigned)(((int)u >> 31) | 0x80000000);
}
__device__ __forceinline__ float unokey(unsigned k) {
    return __uint_as_float((k & 0x80000000u) ? (k ^ 0x80000000u) : ~k);
}

// ---------------- K1: sq norms + bottleneck conv (BN+ReLU), hb transposed ----
__global__ void k_prep(const float* __restrict__ x,
                       const float* __restrict__ Wb, const float* __restrict__ gb,
                       const float* __restrict__ bb, const float* __restrict__ mb,
                       const float* __restrict__ vb)
{
    __shared__ float sW[C_BOT][C_IN];
    __shared__ float sS[C_BOT], sT[C_BOT];
    int tid = threadIdx.x;
    if (tid < C_BOT) {
        float s = gb[tid] * rsqrtf(vb[tid] + EPSBN);
        sS[tid] = s;
        sT[tid] = bb[tid] - mb[tid] * s;
    }
    for (int e = tid; e < C_BOT * C_IN; e += blockDim.x)
        sW[e >> 6][e & 63] = Wb[e];
    __syncthreads();

    int g = blockIdx.x * blockDim.x + tid;      // 0 .. BATCH*N_PTS-1
    if (g >= BATCH * N_PTS) return;
    int b = g >> 12, n = g & (N_PTS - 1);
    const float* xp = x + (size_t)b * C_IN * N_PTS + n;

    float xc[C_IN];
    float sq = 0.f;
#pragma unroll
    for (int c = 0; c < C_IN; c++) {
        float v = xp[(size_t)c * N_PTS];
        xc[c] = v;
        sq += v * v;                 // same ascending-c order as GEMM dot
    }
    g_sq[g] = sq;

#pragma unroll
    for (int o = 0; o < C_BOT; o++) {
        float acc = 0.f;
#pragma unroll
        for (int c = 0; c < C_IN; c++) acc += sW[o][c] * xc[c];
        float h = acc * sS[o] + sT[o];
        g_hb[(size_t)g * C_BOT + o] = fmaxf(h, 0.f);
    }
}

// ------- K2: pairwise squared distances, 128x128 tile, 8x8/thread f32x2 -----
__global__ void __launch_bounds__(256) k_dist(const float* __restrict__ x)
{
    extern __shared__ float smd[];
    float* As  = smd;                  // 64*128
    float* Bs  = As + 64 * 128;        // 64*128
    float* sqA = Bs + 64 * 128;        // 128
    float* sqB = sqA + 128;            // 128

    int b  = blockIdx.z;
    int bi = blockIdx.y;
    int bj = blockIdx.x;
    int tid = threadIdx.x;
    const float* xb = x + (size_t)b * C_IN * N_PTS;

    for (int e = tid; e < 64 * 32; e += 256) {
        int k = e >> 5, i = e & 31;
        ((float4*)As)[k * 32 + i] =
            *(const float4*)&xb[(size_t)k * N_PTS + bi * 128 + i * 4];
        ((float4*)Bs)[k * 32 + i] =
            *(const float4*)&xb[(size_t)k * N_PTS + bj * 128 + i * 4];
    }
    if (tid < 128)      sqA[tid]       = g_sq[b * N_PTS + bi * 128 + tid];
    else                sqB[tid - 128] = g_sq[b * N_PTS + bj * 128 + (tid - 128)];
    __syncthreads();

    int tx = tid & 15, ty = tid >> 4;
    const float4* As4 = (const float4*)As;
    const unsigned long long* Bs8 = (const unsigned long long*)Bs;

    unsigned long long acc2[8][4];
#pragma unroll
    for (int i = 0; i < 8; i++)
#pragma unroll
        for (int j = 0; j < 4; j++) acc2[i][j] = 0ULL;

#pragma unroll 2
    for (int k = 0; k < 64; k++) {
        float4 a0 = As4[k * 32 + ty * 2];
        float4 a1 = As4[k * 32 + ty * 2 + 1];
        unsigned long long B0 = Bs8[k * 64 + tx * 4 + 0];
        unsigned long long B1 = Bs8[k * 64 + tx * 4 + 1];
        unsigned long long B2 = Bs8[k * 64 + tx * 4 + 2];
        unsigned long long B3 = Bs8[k * 64 + tx * 4 + 3];
        unsigned long long A[8];
        A[0] = pk2(a0.x, a0.x); A[1] = pk2(a0.y, a0.y);
        A[2] = pk2(a0.z, a0.z); A[3] = pk2(a0.w, a0.w);
        A[4] = pk2(a1.x, a1.x); A[5] = pk2(a1.y, a1.y);
        A[6] = pk2(a1.z, a1.z); A[7] = pk2(a1.w, a1.w);
#pragma unroll
        for (int i = 0; i < 8; i++) {
            acc2[i][0] = fma2(A[i], B0, acc2[i][0]);
            acc2[i][1] = fma2(A[i], B1, acc2[i][1]);
            acc2[i][2] = fma2(A[i], B2, acc2[i][2]);
            acc2[i][3] = fma2(A[i], B3, acc2[i][3]);
        }
    }

#pragma unroll
    for (int ri = 0; ri < 8; ri++) {
        int r = ty * 8 + ri;
        float sr = sqA[r];
        float c0, c1;
        float4 v0, v1;
        upk2(acc2[ri][0], c0, c1);
        v0.x = sr + sqB[tx * 8 + 0] - 2.f * c0;
        v0.y = sr + sqB[tx * 8 + 1] - 2.f * c1;
        upk2(acc2[ri][1], c0, c1);
        v0.z = sr + sqB[tx * 8 + 2] - 2.f * c0;
        v0.w = sr + sqB[tx * 8 + 3] - 2.f * c1;
        upk2(acc2[ri][2], c0, c1);
        v1.x = sr + sqB[tx * 8 + 4] - 2.f * c0;
        v1.y = sr + sqB[tx * 8 + 5] - 2.f * c1;
        upk2(acc2[ri][3], c0, c1);
        v1.z = sr + sqB[tx * 8 + 6] - 2.f * c0;
        v1.w = sr + sqB[tx * 8 + 7] - 2.f * c1;
        float* dp = g_d2 + ((size_t)(b * N_PTS + bi * 128 + r)) * N_PTS +
                    bj * 128 + tx * 8;
        *(float4*)dp = v0;
        *(float4*)(dp + 4) = v1;
    }
}

// -------- K3: streaming top-K, float prefilter on fma pipe ------------------
__global__ void __launch_bounds__(256) k_topk()
{
    int lane = threadIdx.x & 31, w = threadIdx.x >> 5;
    int row = blockIdx.x * 8 + w;              // b*N + n
    const float* dp = g_d2 + (size_t)row * N_PTS;
    const float INF = __int_as_float(0x7f800000);

    // ---- init: elements 0..31, bitonic sort ascending (packed u64) ----
    unsigned u0 = okey(dp[lane]);
    unsigned long long p = ((unsigned long long)u0 << 32) | (unsigned)lane;
#pragma unroll
    for (int k2 = 2; k2 <= 32; k2 <<= 1) {
#pragma unroll
        for (int j = k2 >> 1; j > 0; j >>= 1) {
            unsigned long long q = __shfl_xor_sync(0xffffffffu, p, j);
            bool up = ((lane & k2) == 0);
            bool lower = ((lane & j) == 0);
            bool takeMin = (up == lower);
            bool qs = q < p;
            p = (takeMin == qs) ? q : p;
        }
    }
    unsigned long long thr = __shfl_sync(0xffffffffu, p, KNN - 1);
    float thrF = unokey((unsigned)(thr >> 32));

    // ---- stream 16 chunks of 256 elements; float-only prefilter ----
#pragma unroll 1
    for (int c = 0; c < 16; c++) {
        float4 va = ((const float4*)dp)[c * 64 + lane];
        float4 vb = ((const float4*)dp)[c * 64 + 32 + lane];
        if (c == 0 && lane < 8) va = make_float4(INF, INF, INF, INF);

        float m0 = fminf(fminf(va.x, va.y), fminf(va.z, va.w));
        float m1 = fminf(fminf(vb.x, vb.y), fminf(vb.z, vb.w));
        float mn = fminf(m0, m1);
        unsigned hit = __ballot_sync(0xffffffffu, mn <= thrF);
        while (hit) {
            int src = __ffs(hit) - 1;
            hit &= hit - 1;
            float f[8];
            f[0] = __shfl_sync(0xffffffffu, va.x, src);
            f[1] = __shfl_sync(0xffffffffu, va.y, src);
            f[2] = __shfl_sync(0xffffffffu, va.z, src);
            f[3] = __shfl_sync(0xffffffffu, va.w, src);
            f[4] = __shfl_sync(0xffffffffu, vb.x, src);
            f[5] = __shfl_sync(0xffffffffu, vb.y, src);
            f[6] = __shfl_sync(0xffffffffu, vb.z, src);
            f[7] = __shfl_sync(0xffffffffu, vb.w, src);
#pragma unroll
            for (int q = 0; q < 8; q++) {
                if (f[q] <= thrF) {            // warp-uniform (shfl'd data)
                    unsigned idx = (unsigned)(c * 256 + (q >> 2) * 128 +
                                              src * 4 + (q & 3));
                    unsigned long long cand =
                        ((unsigned long long)okey(f[q]) << 32) | idx;
                    if (cand < thr) {          // exact final decision
                        unsigned pm = __ballot_sync(0xffffffffu, p < cand);
                        int pos = __popc(pm);
                        unsigned long long up = __shfl_up_sync(0xffffffffu, p, 1);
                        if (lane == pos)      p = cand;
                        else if (lane > pos)  p = up;
                        thr = __shfl_sync(0xffffffffu, p, KNN - 1);
                        thrF = unokey((unsigned)(thr >> 32));
                    }
                }
            }
        }
    }

    if (lane < KNN)
        g_idx[row * KNN + lane] = (int)(p & 0xFFFFFFFFULL);
}

// -------- K4a: fold decoder+residual weights (BN scale) into g_Wt -----------
__global__ void k_fold(const float* __restrict__ Wdec, const float* __restrict__ gdec,
                       const float* __restrict__ bdec, const float* __restrict__ mdec,
                       const float* __restrict__ vdec,
                       const float* __restrict__ Wres, const float* __restrict__ gres,
                       const float* __restrict__ bres, const float* __restrict__ mres,
                       const float* __restrict__ vres)
{
    int tid = blockIdx.x * blockDim.x + threadIdx.x;
    for (int e = tid; e < 160 * 128; e += gridDim.x * blockDim.x) {
        int k = e >> 7, o = e & 127;
        float wv;
        if (k < 96) wv = Wdec[o * 96 + k] * (gdec[o] * rsqrtf(vdec[o] + EPSBN));
        else        wv = Wres[o * 64 + (k - 96)] * (gres[o] * rsqrtf(vres[o] + EPSBN));
        g_Wt[e] = wv;
    }
    if (tid < 128) {
        float sd = gdec[tid] * rsqrtf(vdec[tid] + EPSBN);
        g_bias[tid] = bdec[tid] - mdec[tid] * sd;
        float sr = gres[tid] * rsqrtf(vres[tid] + EPSBN);
        g_bias[128 + tid] = bres[tid] - mres[tid] * sr;
    }
}

// -------- K4b: GCN branches + gmax, one warp per point ----------------------
__global__ void __launch_bounds__(256) k_gcn(
    const float* __restrict__ Wg1, const float* __restrict__ gg1,
    const float* __restrict__ bg1, const float* __restrict__ mg1,
    const float* __restrict__ vg1,
    const float* __restrict__ Wg2, const float* __restrict__ gg2,
    const float* __restrict__ bg2, const float* __restrict__ mg2,
    const float* __restrict__ vg2)
{
    __shared__ float sW1[32 * 33], sW2[32 * 33];
    __shared__ float sS1[32], sS2[32], t1[32], t2[32];
    __shared__ float sNb[8][KNN * 16];
    __shared__ float sCtr[8][16];

    int tid = threadIdx.x, lane = tid & 31, w = tid >> 5;

    if (tid < 32) {
        float s = gg1[tid] * rsqrtf(vg1[tid] + EPSBN);
        sS1[tid] = s; t1[tid] = bg1[tid] - mg1[tid] * s;
        s = gg2[tid] * rsqrtf(vg2[tid] + EPSBN);
        sS2[tid] = s; t2[tid] = bg2[tid] - mg2[tid] * s;
    }
    __syncthreads();
    for (int e = tid; e < 1024; e += 256) {
        int o = e >> 5, c = e & 31;
        sW1[o * 33 + c] = Wg1[e] * sS1[o];
        sW2[o * 33 + c] = Wg2[e] * sS2[o];
    }
    __syncthreads();

    int pt = blockIdx.x * 8 + w;                    // 0 .. B*N-1
    int b = pt >> 12;
    int idxv = (lane < KNN) ? g_idx[pt * KNN + lane] : 0;
    if (lane < 4)
        *(float4*)&sCtr[w][lane * 4] = *(const float4*)&g_hb[(size_t)pt * C_BOT + lane * 4];
#pragma unroll
    for (int t = 0; t < 3; t++) {                   // 80 float4 gathers
        int e = lane + t * 32;
        int row = (e < 80) ? (e >> 2) : 0;
        int ni = __shfl_sync(0xffffffffu, idxv, row);
        if (e < 80) {
            int q = e & 3;
            float4 v = *(const float4*)&g_hb[((size_t)(b << 12) + ni) * C_BOT + q * 4];
            *(float4*)&sNb[w][row * 16 + q * 4] = v;
        }
    }
    __syncwarp();

    float ctr[16];
#pragma unroll
    for (int c = 0; c < 16; c++) ctr[c] = sCtr[w][c];

    float cd1 = t1[lane], cd2 = t2[lane];
#pragma unroll
    for (int c = 0; c < 16; c++) {
        cd1 += sW1[lane * 33 + 16 + c] * ctr[c];
        cd2 += sW2[lane * 33 + 16 + c] * ctr[c];
    }
    float m1 = -FLT_MAX, m2 = -FLT_MAX;
#pragma unroll
    for (int k = 0; k < KNN; k++) {
        float a = cd1;
#pragma unroll
        for (int c = 0; c < 16; c++) a += sW1[lane * 33 + c] * sNb[w][k * 16 + c];
        a = a > 0.f ? a : 0.2f * a;
        m1 = fmaxf(m1, a);
        if ((k & 1) == 0) {
            float a2 = cd2;
#pragma unroll
            for (int c = 0; c < 16; c++) a2 += sW2[lane * 33 + c] * sNb[w][k * 16 + c];
            a2 = a2 > 0.f ? a2 : 0.2f * a2;
            m2 = fmaxf(m2, a2);
        }
    }
    float gm;
    if (lane < 16) {
        gm = -FLT_MAX;
#pragma unroll
        for (int k = 0; k < KNN; k++) gm = fmaxf(gm, sNb[w][k * 16 + lane]);
    } else {
        gm = ctr[lane - 16];
    }
    float* ap = g_allf + (size_t)pt * 96;
    ap[lane] = m1; ap[32 + lane] = m2; ap[64 + lane] = gm;
}

// -------- K4c: decoder+residual GEMM, 128o x 64n tiles ----------------------
#define FPAD 68
__global__ void __launch_bounds__(256) k_dec(const float* __restrict__ x,
                                             float* __restrict__ out)
{
    extern __shared__ float sm[];
    float* sW = sm;                     // 160*128
    float* sF = sW + 160 * 128;         // 16*FPAD
    float* sB = sF + 16 * FPAD;         // 256

    int tid = threadIdx.x;
    int b = blockIdx.y, n0 = blockIdx.x * 64;
    size_t gr0 = (size_t)b * N_PTS + n0;

    for (int e = tid; e < 160 * 128 / 4; e += 256)
        ((float4*)sW)[e] = ((const float4*)g_Wt)[e];
    sB[tid] = g_bias[tid];      // 256 threads cover 256
    __syncthreads();

    int to = tid & 31, tn = tid >> 5;   // o tile of 4, n tile of 8
    float acc[4][8];
    float res[4][8];

    // ---- phase 1: decoder, K=96 from allf ----
#pragma unroll
    for (int i = 0; i < 4; i++)
#pragma unroll
        for (int j = 0; j < 8; j++) acc[i][j] = 0.f;

    for (int kc = 0; kc < 6; kc++) {
        {
            int row = tid >> 2, q = tid & 3;
            float4 v = *(const float4*)&g_allf[(gr0 + row) * 96 + kc * 16 + q * 4];
            sF[(q * 4 + 0) * FPAD + row] = v.x;
            sF[(q * 4 + 1) * FPAD + row] = v.y;
            sF[(q * 4 + 2) * FPAD + row] = v.z;
            sF[(q * 4 + 3) * FPAD + row] = v.w;
        }
        __syncthreads();
#pragma unroll
        for (int k = 0; k < 16; k++) {
            float4 wv = *(float4*)&sW[(kc * 16 + k) * 128 + to * 4];
            float4 f0 = *(float4*)&sF[k * FPAD + tn * 8];
            float4 f1 = *(float4*)&sF[k * FPAD + tn * 8 + 4];
            float wr[4] = {wv.x, wv.y, wv.z, wv.w};
            float fr[8] = {f0.x, f0.y, f0.z, f0.w, f1.x, f1.y, f1.z, f1.w};
#pragma unroll
            for (int i = 0; i < 4; i++)
#pragma unroll
                for (int j = 0; j < 8; j++) acc[i][j] += wr[i] * fr[j];
        }
        __syncthreads();
    }
#pragma unroll
    for (int i = 0; i < 4; i++) {
        float bv = sB[to * 4 + i];
#pragma unroll
        for (int j = 0; j < 8; j++) {
            res[i][j] = fmaxf(acc[i][j] + bv, 0.f);
            acc[i][j] = 0.f;
        }
    }

    // ---- phase 2: residual, K=64 from x (coalesced channel rows) ----
    for (int kc = 0; kc < 4; kc++) {
        {
            int c = tid >> 4, nq = tid & 15;
            float4 v = *(const float4*)&x[((size_t)(b * C_IN + kc * 16 + c)) * N_PTS +
                                          n0 + nq * 4];
            *(float4*)&sF[c * FPAD + nq * 4] = v;
        }
        __syncthreads();
#pragma unroll
        for (int k = 0; k < 16; k++) {
            float4 wv = *(float4*)&sW[(96 + kc * 16 + k) * 128 + to * 4];
            float4 f0 = *(float4*)&sF[k * FPAD + tn * 8];
            float4 f1 = *(float4*)&sF[k * FPAD + tn * 8 + 4];
            float wr[4] = {wv.x, wv.y, wv.z, wv.w};
            float fr[8] = {f0.x, f0.y, f0.z, f0.w, f1.x, f1.y, f1.z, f1.w};
#pragma unroll
            for (int i = 0; i < 4; i++)
#pragma unroll
                for (int j = 0; j < 8; j++) acc[i][j] += wr[i] * fr[j];
        }
        __syncthreads();
    }

#pragma unroll
    for (int i = 0; i < 4; i++) {
        int o = to * 4 + i;
        float bv = sB[128 + o];
        float4 r0, r1;
        r0.x = res[i][0] + fmaxf(acc[i][0] + bv, 0.f);
        r0.y = res[i][1] + fmaxf(acc[i][1] + bv, 0.f);
        r0.z = res[i][2] + fmaxf(acc[i][2] + bv, 0.f);
        r0.w = res[i][3] + fmaxf(acc[i][3] + bv, 0.f);
        r1.x = res[i][4] + fmaxf(acc[i][4] + bv, 0.f);
        r1.y = res[i][5] + fmaxf(acc[i][5] + bv, 0.f);
        r1.z = res[i][6] + fmaxf(acc[i][6] + bv, 0.f);
        r1.w = res[i][7] + fmaxf(acc[i][7] + bv, 0.f);
        float* op = out + ((size_t)(b * C_OUT + o)) * N_PTS + n0 + tn * 8;
        *(float4*)op = r0;
        *(float4*)(op + 4) = r1;
    }
}

// ---------------- launch -----------------------------------------------------
extern "C" void kernel_launch(void* const* d_in, const int* in_sizes, int n_in,
                              void* d_out, int out_size)
{
    const float* x    = (const float*)d_in[0];
    const float* Wres = (const float*)d_in[1];
    const float* gres = (const float*)d_in[2];
    const float* bres = (const float*)d_in[3];
    const float* mres = (const float*)d_in[4];
    const float* vres = (const float*)d_in[5];
    const float* Wbot = (const float*)d_in[6];
    const float* gbot = (const float*)d_in[7];
    const float* bbot = (const float*)d_in[8];
    const float* mbot = (const float*)d_in[9];
    const float* vbot = (const float*)d_in[10];
    const float* Wg1  = (const float*)d_in[11];
    const float* gg1  = (const float*)d_in[12];
    const float* bg1  = (const float*)d_in[13];
    const float* mg1  = (const float*)d_in[14];
    const float* vg1  = (const float*)d_in[15];
    const float* Wg2  = (const float*)d_in[16];
    const float* gg2  = (const float*)d_in[17];
    const float* bg2  = (const float*)d_in[18];
    const float* mg2  = (const float*)d_in[19];
    const float* vg2  = (const float*)d_in[20];
    const float* Wdec = (const float*)d_in[21];
    const float* gdec = (const float*)d_in[22];
    const float* bdec = (const float*)d_in[23];
    const float* mdec = (const float*)d_in[24];
    const float* vdec = (const float*)d_in[25];
    float* out = (float*)d_out;

    size_t smem_dist = (64 * 128 * 2 + 256) * sizeof(float);
    cudaFuncSetAttribute(k_dist, cudaFuncAttributeMaxDynamicSharedMemorySize,
                         (int)smem_dist);
    size_t smem_dec = (160 * 128 + 16 * FPAD + 256) * sizeof(float);
    cudaFuncSetAttribute(k_dec, cudaFuncAttributeMaxDynamicSharedMemorySize,
                         (int)smem_dec);

    k_prep<<<(BATCH * N_PTS + 255) / 256, 256>>>(x, Wbot, gbot, bbot, mbot, vbot);
    k_fold<<<80, 256>>>(Wdec, gdec, bdec, mdec, vdec, Wres, gres, bres, mres, vres);
    k_dist<<<dim3(N_PTS / 128, N_PTS / 128, BATCH), 256, smem_dist>>>(x);
    k_topk<<<BATCH * N_PTS / 8, 256>>>();
    k_gcn<<<BATCH * N_PTS / 8, 256>>>(Wg1, gg1, bg1, mg1, vg1,
                                      Wg2, gg2, bg2, mg2, vg2);
    k_dec<<<dim3(N_PTS / 64, BATCH), 256, smem_dec>>>(x, out);
}